// round 4
// baseline (speedup 1.0000x reference)
#include <cuda_runtime.h>

#define NN 50000
#define EE 800000
#define DD 64
#define HHD 8   // heads
#define CC 8    // head dim
#define LLAY 5

// ---------------- device scratch (static, no allocation) ----------------
__device__ float g_h [NN * DD];     // current node features
__device__ float g_hp[NN * DD];     // per-layer transformed features
__device__ float g_ai[NN * HHD];    // per-node dot with att[:, :C]  (dst side)
__device__ float g_aj[NN * HHD];    // per-node dot with att[:, C:]  (src side)
__device__ int   g_rowptr[NN + 1];
__device__ int   g_wp[NN];          // degree counter, then write pointer
__device__ int   g_srcs[EE];        // edge sources sorted by dst (CSR)

// ---------------- CSR build ----------------
__global__ void k_zero()
{
    int i = blockIdx.x * blockDim.x + threadIdx.x;
    if (i < NN) g_wp[i] = 0;
}

__global__ void k_count(const int* __restrict__ dst)
{
    int e = blockIdx.x * blockDim.x + threadIdx.x;
    if (e < EE) atomicAdd(&g_wp[dst[e]], 1);
}

__global__ void k_scan()
{
    __shared__ int sh[1024];
    const int CH = (NN + 1023) / 1024;  // 49
    int t  = threadIdx.x;
    int s0 = t * CH;
    int s1 = s0 + CH; if (s1 > NN) s1 = NN;
    int loc = 0;
    for (int i = s0; i < s1; i++) loc += g_wp[i];
    sh[t] = loc;
    __syncthreads();
    if (t == 0) {
        int run = 0;
        for (int i = 0; i < 1024; i++) { int v = sh[i]; sh[i] = run; run += v; }
        g_rowptr[NN] = run;   // == EE
    }
    __syncthreads();
    int run = sh[t];
    for (int i = s0; i < s1; i++) {
        int d = g_wp[i];
        g_rowptr[i] = run;
        g_wp[i]     = run;    // write pointer starts at segment begin
        run += d;
    }
}

__global__ void k_scatter(const int* __restrict__ src, const int* __restrict__ dst)
{
    int e = blockIdx.x * blockDim.x + threadIdx.x;
    if (e < EE) {
        int p = atomicAdd(&g_wp[dst[e]], 1);
        g_srcs[p] = src[e];
    }
}

// ---------------- GEMM: out = X @ W + b  (+optional relu / attention scalars) ----------------
// mode 0: out = relu(X@W+b)            (input embedding -> g_h)
// mode 1: out = X@W+b, also g_ai/g_aj  (layer linear   -> g_hp)
__global__ void __launch_bounds__(128) k_gemm(
    const float* __restrict__ X, const float* __restrict__ W,
    const float* __restrict__ bias, const float* __restrict__ att,
    float* __restrict__ out, int mode)
{
    __shared__ float Ws[DD * DD];
    __shared__ float bs[DD];
    __shared__ float as[2 * HHD * CC];  // 128

    int tid = threadIdx.x;
    for (int i = tid; i < DD * DD; i += 128) Ws[i] = W[i];
    if (tid < DD) bs[tid] = bias[tid];
    if (mode) as[tid] = att[tid];       // exactly 128 floats
    __syncthreads();

    int r = blockIdx.x * 128 + tid;
    if (r >= NN) return;

    float acc[DD];
#pragma unroll
    for (int c = 0; c < DD; c++) acc[c] = bs[c];

    const float* xr = X + (size_t)r * DD;
    for (int k0 = 0; k0 < DD; k0 += 4) {
        float4 xv = *(const float4*)(xr + k0);
        float xs[4] = {xv.x, xv.y, xv.z, xv.w};
#pragma unroll
        for (int kk = 0; kk < 4; kk++) {
            float xk = xs[kk];
            const float* wr = &Ws[(k0 + kk) * DD];
#pragma unroll
            for (int c = 0; c < DD; c++) acc[c] += xk * wr[c];
        }
    }

    if (mode == 0) {
#pragma unroll
        for (int c = 0; c < DD; c++) acc[c] = acc[c] > 0.f ? acc[c] : 0.f;
    } else {
        // per-head attention scalars
#pragma unroll
        for (int h = 0; h < HHD; h++) {
            float ai = 0.f, aj = 0.f;
#pragma unroll
            for (int c = 0; c < CC; c++) {
                float v = acc[h * CC + c];
                ai += v * as[h * 2 * CC + c];
                aj += v * as[h * 2 * CC + CC + c];
            }
            g_ai[r * HHD + h] = ai;
            g_aj[r * HHD + h] = aj;
        }
    }

    float* orow = out + (size_t)r * DD;
#pragma unroll
    for (int c4 = 0; c4 < DD; c4 += 4) {
        float4 v = make_float4(acc[c4], acc[c4 + 1], acc[c4 + 2], acc[c4 + 3]);
        *(float4*)(orow + c4) = v;
    }
}

// ---------------- fused GAT: softmax + aggregate + bias + ELU + LayerNorm ----------------
// one warp per destination node
__global__ void __launch_bounds__(256) k_gat(
    const float* __restrict__ ob, const float* __restrict__ lng,
    const float* __restrict__ lnb, float* __restrict__ out)
{
    int warp = threadIdx.x >> 5;
    int lane = threadIdx.x & 31;
    int node = blockIdx.x * (blockDim.x >> 5) + warp;
    if (node >= NN) return;

    int beg = g_rowptr[node];
    int end = g_rowptr[node + 1];

    int hh = lane >> 2;       // head 0..7 (4 lanes per head)
    int jj = lane & 3;
    float ai = g_ai[node * HHD + hh];

    // ---- pass 1: per-head softmax denominator (no max-shift; logits are tiny) ----
    float ssum = 0.f;
    for (int e = beg + jj; e < end; e += 4) {
        int s = g_srcs[e];
        float al = ai + g_aj[s * HHD + hh];
        al = al > 0.f ? al : 0.2f * al;
        ssum += __expf(al);
    }
    ssum += __shfl_xor_sync(0xffffffffu, ssum, 1);
    ssum += __shfl_xor_sync(0xffffffffu, ssum, 2);
    float inv_s = 1.f / (ssum + 1e-16f);

    // ---- pass 2: weighted feature aggregation (2 channels per lane) ----
    float a0 = 0.f, a1 = 0.f;
    int ch = lane * 2;
    for (int e = beg; e < end; e++) {
        int s = g_srcs[e];
        float al = ai + g_aj[s * HHD + hh];
        al = al > 0.f ? al : 0.2f * al;
        float w = __expf(al) * inv_s;
        float2 hv = *(const float2*)(g_hp + (size_t)s * DD + ch);
        a0 += hv.x * w;
        a1 += hv.y * w;
    }

    // bias + ELU
    a0 += ob[ch];
    a1 += ob[ch + 1];
    a0 = a0 > 0.f ? a0 : (__expf(a0) - 1.f);
    a1 = a1 > 0.f ? a1 : (__expf(a1) - 1.f);

    // LayerNorm over 64 channels (warp reduce)
    float sum = a0 + a1;
    float sq  = a0 * a0 + a1 * a1;
#pragma unroll
    for (int o = 16; o >= 1; o >>= 1) {
        sum += __shfl_xor_sync(0xffffffffu, sum, o);
        sq  += __shfl_xor_sync(0xffffffffu, sq,  o);
    }
    float mu  = sum * (1.f / 64.f);
    float var = sq * (1.f / 64.f) - mu * mu;
    float rs  = rsqrtf(var + 1e-5f);
    float y0  = (a0 - mu) * rs * lng[ch]     + lnb[ch];
    float y1  = (a1 - mu) * rs * lng[ch + 1] + lnb[ch + 1];
    *(float2*)(out + (size_t)node * DD + ch) = make_float2(y0, y1);
}

// ---------------- launch ----------------
extern "C" void kernel_launch(void* const* d_in, const int* in_sizes, int n_in,
                              void* d_out, int out_size)
{
    const float* x     = (const float*)d_in[0];
    const int*   ei    = (const int*)  d_in[1];   // [2, E]
    const float* W_in  = (const float*)d_in[2];
    const float* b_in  = (const float*)d_in[3];
    const float* lin_w = (const float*)d_in[4];   // [L, D, D]
    const float* lin_b = (const float*)d_in[5];   // [L, D]
    const float* att   = (const float*)d_in[6];   // [L, H, 2C]
    const float* obias = (const float*)d_in[7];   // [L, D]
    const float* ln_g  = (const float*)d_in[8];
    const float* ln_b  = (const float*)d_in[9];
    float* out = (float*)d_out;

    float* p_h;  cudaGetSymbolAddress((void**)&p_h,  g_h);
    float* p_hp; cudaGetSymbolAddress((void**)&p_hp, g_hp);

    const int* src = ei;
    const int* dst = ei + EE;

    // CSR by destination (rebuilt deterministically each call)
    k_zero   <<<(NN + 255) / 256, 256>>>();
    k_count  <<<(EE + 255) / 256, 256>>>(dst);
    k_scan   <<<1, 1024>>>();
    k_scatter<<<(EE + 255) / 256, 256>>>(src, dst);

    const int GB = (NN + 127) / 128;      // gemm grid
    const int AB = (NN + 7) / 8;          // gat grid (8 warps/block)

    // input embedding: h = relu(x @ W_in + b_in)
    k_gemm<<<GB, 128>>>(x, W_in, b_in, nullptr, p_h, 0);

    for (int l = 0; l < LLAY; l++) {
        k_gemm<<<GB, 128>>>(p_h, lin_w + (size_t)l * DD * DD, lin_b + l * DD,
                            att + l * 2 * HHD * CC, p_hp, 1);
        float* dstbuf = (l == LLAY - 1) ? out : p_h;
        k_gat<<<AB, 256>>>(obias + l * DD, ln_g + l * DD, ln_b + l * DD, dstbuf);
    }
}

// round 6
// speedup vs baseline: 1.0798x; 1.0798x over previous
#include <cuda_runtime.h>

#define NN 50000
#define EE 800000
#define DD 64
#define HHD 8   // heads
#define CC 8    // head dim
#define LLAY 5

// ---------------- device scratch (static, no allocation) ----------------
__device__ float g_h [NN * DD];     // current node features
__device__ float g_hp[NN * DD];     // per-layer transformed features
__device__ float g_ai[NN * HHD];    // per-node dot with att[:, :C]  (dst side)
__device__ float g_aj[NN * HHD];    // per-node dot with att[:, C:]  (src side)
__device__ int   g_rowptr[NN + 1];
__device__ int   g_wp[NN];          // degree counter, then write pointer
__device__ int   g_srcs[EE];        // edge sources sorted by dst (CSR)

// ---------------- CSR build ----------------
__global__ void k_zero()
{
    int i = blockIdx.x * blockDim.x + threadIdx.x;
    if (i < NN) g_wp[i] = 0;
}

__global__ void k_count(const int* __restrict__ dst)
{
    int e = blockIdx.x * blockDim.x + threadIdx.x;
    if (e < EE) atomicAdd(&g_wp[dst[e]], 1);
}

__global__ void k_scan()
{
    __shared__ int sh[1024];
    const int CH = (NN + 1023) / 1024;  // 49
    int t  = threadIdx.x;
    int s0 = t * CH;
    int s1 = s0 + CH; if (s1 > NN) s1 = NN;
    int loc = 0;
    for (int i = s0; i < s1; i++) loc += g_wp[i];
    sh[t] = loc;
    __syncthreads();
    if (t == 0) {
        int run = 0;
        for (int i = 0; i < 1024; i++) { int v = sh[i]; sh[i] = run; run += v; }
        g_rowptr[NN] = run;   // == EE
    }
    __syncthreads();
    int run = sh[t];
    for (int i = s0; i < s1; i++) {
        int d = g_wp[i];
        g_rowptr[i] = run;
        g_wp[i]     = run;    // write pointer starts at segment begin
        run += d;
    }
}

__global__ void k_scatter(const int* __restrict__ src, const int* __restrict__ dst)
{
    int e = blockIdx.x * blockDim.x + threadIdx.x;
    if (e < EE) {
        int p = atomicAdd(&g_wp[dst[e]], 1);
        g_srcs[p] = src[e];
    }
}

// ---------------- GEMM: out = X @ W + b  (+optional relu / attention scalars) ----------------
__global__ void __launch_bounds__(128) k_gemm(
    const float* __restrict__ X, const float* __restrict__ W,
    const float* __restrict__ bias, const float* __restrict__ att,
    float* __restrict__ out, int mode)
{
    __shared__ float Ws[DD * DD];
    __shared__ float bs[DD];
    __shared__ float as[2 * HHD * CC];  // 128

    int tid = threadIdx.x;
    for (int i = tid; i < DD * DD; i += 128) Ws[i] = W[i];
    if (tid < DD) bs[tid] = bias[tid];
    if (mode) as[tid] = att[tid];       // exactly 128 floats
    __syncthreads();

    int r = blockIdx.x * 128 + tid;
    if (r >= NN) return;

    float acc[DD];
#pragma unroll
    for (int c = 0; c < DD; c++) acc[c] = bs[c];

    const float* xr = X + (size_t)r * DD;
    for (int k0 = 0; k0 < DD; k0 += 4) {
        float4 xv = *(const float4*)(xr + k0);
        float xs[4] = {xv.x, xv.y, xv.z, xv.w};
#pragma unroll
        for (int kk = 0; kk < 4; kk++) {
            float xk = xs[kk];
            const float* wr = &Ws[(k0 + kk) * DD];
#pragma unroll
            for (int c = 0; c < DD; c++) acc[c] += xk * wr[c];
        }
    }

    if (mode == 0) {
#pragma unroll
        for (int c = 0; c < DD; c++) acc[c] = acc[c] > 0.f ? acc[c] : 0.f;
    } else {
        // per-head attention scalars
#pragma unroll
        for (int h = 0; h < HHD; h++) {
            float ai = 0.f, aj = 0.f;
#pragma unroll
            for (int c = 0; c < CC; c++) {
                float v = acc[h * CC + c];
                ai += v * as[h * 2 * CC + c];
                aj += v * as[h * 2 * CC + CC + c];
            }
            g_ai[r * HHD + h] = ai;
            g_aj[r * HHD + h] = aj;
        }
    }

    float* orow = out + (size_t)r * DD;
#pragma unroll
    for (int c4 = 0; c4 < DD; c4 += 4) {
        float4 v = make_float4(acc[c4], acc[c4 + 1], acc[c4 + 2], acc[c4 + 3]);
        *(float4*)(orow + c4) = v;
    }
}

// ---------------- fused GAT: SINGLE-PASS softmax+aggregate + bias + ELU + LN ----------------
// one warp per destination node; softmax normalization applied post-hoc:
//   agg = sum_k exp(a_k) x_k / sum_k exp(a_k)
__global__ void __launch_bounds__(256) k_gat(
    const float* __restrict__ ob, const float* __restrict__ lng,
    const float* __restrict__ lnb, float* __restrict__ out)
{
    int warp = threadIdx.x >> 5;
    int lane = threadIdx.x & 31;
    int node = blockIdx.x * (blockDim.x >> 5) + warp;
    if (node >= NN) return;

    int beg = g_rowptr[node];
    int end = g_rowptr[node + 1];

    int hh = lane >> 2;       // head 0..7
    int ch = lane * 2;        // channel pair handled by this lane
    float ai = g_ai[node * HHD + hh];

    float a0 = 0.f, a1 = 0.f, ssum = 0.f;

    int e = beg;
    // unroll x4: 4 independent aj gathers + 4 independent 256B row gathers in flight
    for (; e + 4 <= end; e += 4) {
        int s0 = g_srcs[e];
        int s1 = g_srcs[e + 1];
        int s2 = g_srcs[e + 2];
        int s3 = g_srcs[e + 3];
        float j0 = g_aj[s0 * HHD + hh];
        float j1 = g_aj[s1 * HHD + hh];
        float j2 = g_aj[s2 * HHD + hh];
        float j3 = g_aj[s3 * HHD + hh];
        float2 v0 = *(const float2*)(g_hp + (size_t)s0 * DD + ch);
        float2 v1 = *(const float2*)(g_hp + (size_t)s1 * DD + ch);
        float2 v2 = *(const float2*)(g_hp + (size_t)s2 * DD + ch);
        float2 v3 = *(const float2*)(g_hp + (size_t)s3 * DD + ch);

        float l0 = ai + j0; l0 = l0 > 0.f ? l0 : 0.2f * l0;
        float l1 = ai + j1; l1 = l1 > 0.f ? l1 : 0.2f * l1;
        float l2 = ai + j2; l2 = l2 > 0.f ? l2 : 0.2f * l2;
        float l3 = ai + j3; l3 = l3 > 0.f ? l3 : 0.2f * l3;
        float w0 = __expf(l0);
        float w1 = __expf(l1);
        float w2 = __expf(l2);
        float w3 = __expf(l3);
        ssum += (w0 + w1) + (w2 + w3);
        a0 += v0.x * w0 + v1.x * w1 + v2.x * w2 + v3.x * w3;
        a1 += v0.y * w0 + v1.y * w1 + v2.y * w2 + v3.y * w3;
    }
    for (; e < end; e++) {
        int s = g_srcs[e];
        float al = ai + g_aj[s * HHD + hh];
        al = al > 0.f ? al : 0.2f * al;
        float w = __expf(al);
        float2 hv = *(const float2*)(g_hp + (size_t)s * DD + ch);
        ssum += w;
        a0 += hv.x * w;
        a1 += hv.y * w;
    }

    float inv_s = 1.f / (ssum + 1e-16f);
    a0 *= inv_s;
    a1 *= inv_s;

    // bias + ELU
    a0 += ob[ch];
    a1 += ob[ch + 1];
    a0 = a0 > 0.f ? a0 : (__expf(a0) - 1.f);
    a1 = a1 > 0.f ? a1 : (__expf(a1) - 1.f);

    // LayerNorm over 64 channels (warp reduce)
    float sum = a0 + a1;
    float sq  = a0 * a0 + a1 * a1;
#pragma unroll
    for (int o = 16; o >= 1; o >>= 1) {
        sum += __shfl_xor_sync(0xffffffffu, sum, o);
        sq  += __shfl_xor_sync(0xffffffffu, sq,  o);
    }
    float mu  = sum * (1.f / 64.f);
    float var = sq * (1.f / 64.f) - mu * mu;
    float rs  = rsqrtf(var + 1e-5f);
    float y0  = (a0 - mu) * rs * lng[ch]     + lnb[ch];
    float y1  = (a1 - mu) * rs * lng[ch + 1] + lnb[ch + 1];
    *(float2*)(out + (size_t)node * DD + ch) = make_float2(y0, y1);
}

// ---------------- launch ----------------
extern "C" void kernel_launch(void* const* d_in, const int* in_sizes, int n_in,
                              void* d_out, int out_size)
{
    const float* x     = (const float*)d_in[0];
    const int*   ei    = (const int*)  d_in[1];   // [2, E]
    const float* W_in  = (const float*)d_in[2];
    const float* b_in  = (const float*)d_in[3];
    const float* lin_w = (const float*)d_in[4];   // [L, D, D]
    const float* lin_b = (const float*)d_in[5];   // [L, D]
    const float* att   = (const float*)d_in[6];   // [L, H, 2C]
    const float* obias = (const float*)d_in[7];   // [L, D]
    const float* ln_g  = (const float*)d_in[8];
    const float* ln_b  = (const float*)d_in[9];
    float* out = (float*)d_out;

    float* p_h;  cudaGetSymbolAddress((void**)&p_h,  g_h);
    float* p_hp; cudaGetSymbolAddress((void**)&p_hp, g_hp);

    const int* src = ei;
    const int* dst = ei + EE;

    // CSR by destination (rebuilt deterministically each call)
    k_zero   <<<(NN + 255) / 256, 256>>>();
    k_count  <<<(EE + 255) / 256, 256>>>(dst);
    k_scan   <<<1, 1024>>>();
    k_scatter<<<(EE + 255) / 256, 256>>>(src, dst);

    const int GB = (NN + 127) / 128;      // gemm grid
    const int AB = (NN + 7) / 8;          // gat grid (8 warps/block)

    // input embedding: h = relu(x @ W_in + b_in)
    k_gemm<<<GB, 128>>>(x, W_in, b_in, nullptr, p_h, 0);

    for (int l = 0; l < LLAY; l++) {
        k_gemm<<<GB, 128>>>(p_h, lin_w + (size_t)l * DD * DD, lin_b + l * DD,
                            att + l * 2 * HHD * CC, p_hp, 1);
        float* dstbuf = (l == LLAY - 1) ? out : p_h;
        k_gat<<<AB, 256>>>(obias + l * DD, ln_g + l * DD, ln_b + l * DD, dstbuf);
    }
}